// round 3
// baseline (speedup 1.0000x reference)
#include <cuda_runtime.h>
#include <math.h>

#define NJ 140
#define NV 13059
#define NB 28
#define BATCH 512
#define VPAD 13184        // 103 * 128
#define VT 128
#define BT 16
#define KC 28

typedef unsigned long long ull;

// Scratch (device globals; no allocations allowed)
__device__ float g_G[BATCH * NJ * 12];    // folded skinning matrices [b][j][3x4 row-major]
__device__ float g_Wt[NJ * VPAD];         // transposed weights [j][v], zero-padded

// ---- packed f32x2 helpers -------------------------------------------------
__device__ __forceinline__ ull pk2(float lo, float hi) {
    ull r; asm("mov.b64 %0, {%1, %2};" : "=l"(r) : "f"(lo), "f"(hi)); return r;
}
__device__ __forceinline__ ull fma2(ull a, ull b, ull c) {
    ull d; asm("fma.rn.f32x2 %0, %1, %2, %3;" : "=l"(d) : "l"(a), "l"(b), "l"(c)); return d;
}
__device__ __forceinline__ float2 unpk2(ull a) {
    float2 f; asm("mov.b64 {%0, %1}, %2;" : "=f"(f.x), "=f"(f.y) : "l"(a)); return f;
}

// ---------------------------------------------------------------------------
// Kernel 0: transpose weights (13059 x 140) -> (140 x VPAD), pad with zeros
// ---------------------------------------------------------------------------
__global__ void transpose_w_kernel(const float* __restrict__ W) {
    __shared__ float tile[32][33];
    int j0 = blockIdx.x * 32;
    int v0 = blockIdx.y * 32;
    int tx = threadIdx.x, ty = threadIdx.y;   // blockDim (32, 8)
    #pragma unroll
    for (int k = 0; k < 4; k++) {
        int v = v0 + ty + k * 8;
        int j = j0 + tx;
        float val = 0.f;
        if (v < NV && j < NJ) val = W[v * NJ + j];
        tile[ty + k * 8][tx] = val;
    }
    __syncthreads();
    #pragma unroll
    for (int k = 0; k < 4; k++) {
        int j = j0 + ty + k * 8;
        int v = v0 + tx;
        if (j < NJ && v < VPAD) g_Wt[j * VPAD + v] = tile[tx][ty + k * 8];
    }
}

// ---------------------------------------------------------------------------
// Kernel 1: per-batch skeleton. One warp per batch element.
// ---------------------------------------------------------------------------
__global__ void skeleton_kernel(const float* __restrict__ pose,
                                const float* __restrict__ bone_lengths,
                                const float* __restrict__ cbl,
                                const float* __restrict__ trans,
                                const float* __restrict__ scale,
                                const float* __restrict__ Jt,
                                const int*   __restrict__ parent,
                                const int*   __restrict__ bone_mapper,
                                float* __restrict__ out_J) {
    __shared__ float M[4][NJ * 12];
    __shared__ int par_s[NJ];
    int lane = threadIdx.x & 31;
    int w    = threadIdx.x >> 5;
    int b    = blockIdx.x * 4 + w;

    for (int i = threadIdx.x; i < NJ; i += 128) par_s[i] = parent[i];
    __syncthreads();

    float* Mw = M[w];

    // ---- Phase A: local transforms ----
    for (int j = lane; j < NJ; j += 32) {
        float z = pose[b * NJ * 3 + j * 3 + 0];
        float y = pose[b * NJ * 3 + j * 3 + 1];
        float x = pose[b * NJ * 3 + j * 3 + 2];
        float cx, sx, cy, sy, cz, sz;
        sincosf(x, &sx, &cx);
        sincosf(y, &sy, &cy);
        sincosf(z, &sz, &cz);
        float r00 = cz * cy, r01 = cz * sy * sx - sz * cx, r02 = cz * sy * cx + sz * sx;
        float r10 = sz * cy, r11 = sz * sy * sx + cz * cx, r12 = sz * sy * cx - cz * sx;
        float r20 = -sy,     r21 = cy * sx,                r22 = cy * cx;
        float t0, t1, t2;
        if (j == 0) {
            t0 = Jt[0]; t1 = Jt[1]; t2 = Jt[2];
        } else {
            int p = par_s[j];
            float ox = Jt[j * 3 + 0] - Jt[p * 3 + 0];
            float oy = Jt[j * 3 + 1] - Jt[p * 3 + 1];
            float oz = Jt[j * 3 + 2] - Jt[p * 3 + 2];
            float sc;
            if (j == 1) {
                sc = cbl[b];
            } else {
                int blid = bone_mapper[j];
                if (blid >= 0) {
                    float bv = bone_lengths[b * NB + blid];
                    sc = 2.f / (1.f + expf(-bv * 0.2f));   // 2*sigmoid(x/5)
                } else {
                    sc = 1.f;
                }
            }
            t0 = ox * sc; t1 = oy * sc; t2 = oz * sc;
        }
        float* d = Mw + j * 12;
        d[0] = r00; d[1] = r01; d[2]  = r02; d[3]  = t0;
        d[4] = r10; d[5] = r11; d[6]  = r12; d[7]  = t1;
        d[8] = r20; d[9] = r21; d[10] = r22; d[11] = t2;
    }
    __syncwarp();

    // ---- Phase B: serial kinematic chain ----
    int m = lane >> 2, n = lane & 3;
    for (int i = 1; i < NJ; i++) {
        int p = par_s[i];
        float val = 0.f;
        if (lane < 12) {
            float a0 = Mw[p * 12 + m * 4 + 0];
            float a1 = Mw[p * 12 + m * 4 + 1];
            float a2 = Mw[p * 12 + m * 4 + 2];
            float b0 = Mw[i * 12 + 0 + n];
            float b1 = Mw[i * 12 + 4 + n];
            float b2 = Mw[i * 12 + 8 + n];
            val = fmaf(a0, b0, fmaf(a1, b1, a2 * b2));
            if (n == 3) val += Mw[p * 12 + m * 4 + 3];
        }
        __syncwarp();
        if (lane < 12) Mw[i * 12 + lane] = val;
        __syncwarp();
    }

    // ---- Phase C: outputs ----
    float s   = scale[b];
    float trx = trans[b * 3 + 0];
    float try_ = trans[b * 3 + 1];
    float trz = trans[b * 3 + 2];
    for (int j = lane; j < NJ; j += 32) {
        const float* d = Mw + j * 12;
        float r00 = d[0], r01 = d[1], r02 = d[2],  t0 = d[3];
        float r10 = d[4], r11 = d[5], r12 = d[6],  t1 = d[7];
        float r20 = d[8], r21 = d[9], r22 = d[10], t2 = d[11];

        float* jo = out_J + ((size_t)b * NJ + j) * 3;
        jo[0] = fmaf(t0, s, trx);
        jo[1] = fmaf(t1, s, try_);
        jo[2] = fmaf(t2, s, trz);

        float jtx = Jt[j * 3 + 0], jty = Jt[j * 3 + 1], jtz = Jt[j * 3 + 2];
        float g0 = s * (t0 - (r00 * jtx + r01 * jty + r02 * jtz)) + trx;
        float g1 = s * (t1 - (r10 * jtx + r11 * jty + r12 * jtz)) + try_;
        float g2 = s * (t2 - (r20 * jtx + r21 * jty + r22 * jtz)) + trz;
        float* g = g_G + ((size_t)b * NJ + j) * 12;
        g[0] = s * r00; g[1] = s * r01; g[2]  = s * r02; g[3]  = g0;
        g[4] = s * r10; g[5] = s * r11; g[6]  = s * r12; g[7]  = g1;
        g[8] = s * r20; g[9] = s * r21; g[10] = s * r22; g[11] = g2;
    }
}

// ---------------------------------------------------------------------------
// Kernel 2: skinning with packed f32x2 FMA.
// Block = 256 threads, tile = 128 vertices x 16 batches.
// Thread owns 4 vertices (vth + 32r) and the batch PAIR (bth, bth+8), packed
// into f32x2 lanes. G staged in SMEM interleaved {comp_s0, comp_s1} so two
// LDS.128 per row yield packed operands directly.
// ---------------------------------------------------------------------------
__global__ void __launch_bounds__(256, 2) skin_kernel(const float* __restrict__ vtemp,
                                                      float* __restrict__ out_V) {
    __shared__ __align__(16) float w_s[KC * VT];            // [j][v]        14 KB
    __shared__ __align__(16) float g_s[KC * 3 * 8 * 8];     // packed G      21 KB

    int tx  = threadIdx.x;
    int vth = tx & 31;
    int bth = tx >> 5;               // 0..7 : batch pair (b0+bth, b0+bth+8)
    int v0  = blockIdx.x * VT;
    int b0  = blockIdx.y * BT;

    // q vectors, packed {q, q}
    ull qx2[4], qy2[4], qz2[4];
    #pragma unroll
    for (int r = 0; r < 4; r++) {
        int v = v0 + vth + 32 * r;
        float qx = 0.f, qy = 0.f, qz = 0.f;
        if (v < NV) {
            qx = vtemp[v * 3 + 0];
            qy = vtemp[v * 3 + 1];
            qz = vtemp[v * 3 + 2];
        }
        qx2[r] = pk2(qx, qx);
        qy2[r] = pk2(qy, qy);
        qz2[r] = pk2(qz, qz);
    }

    ull acc[4][3];
    ull zero = pk2(0.f, 0.f);
    #pragma unroll
    for (int r = 0; r < 4; r++) {
        acc[r][0] = zero; acc[r][1] = zero; acc[r][2] = zero;
    }

    const float4* gsrc = (const float4*)g_G;     // 420 float4 per batch

    for (int k0 = 0; k0 < NJ; k0 += KC) {
        __syncthreads();
        // stage weights chunk: 896 float4
        #pragma unroll
        for (int i = 0; i < 4; i++) {
            int idx4 = tx + i * 256;
            if (idx4 < (KC * VT) / 4) {
                int j = idx4 >> 5, vl = idx4 & 31;
                ((float4*)w_s)[idx4] =
                    ((const float4*)(g_Wt + (size_t)(k0 + j) * VPAD + v0))[vl];
            }
        }
        // stage G chunk interleaved: dst float = ((j*3+m)*8 + (b&7))*8 + n*2 + (b>>3)
        #pragma unroll
        for (int i = 0; i < 6; i++) {
            int idx4 = tx + i * 256;
            if (idx4 < BT * KC * 3) {
                int b   = idx4 / (KC * 3);
                int rem = idx4 - b * (KC * 3);
                int j   = rem / 3;
                int m   = rem - j * 3;
                float4 g = gsrc[(size_t)(b0 + b) * (NJ * 3) + (size_t)(k0 + j) * 3 + m];
                int base = (((j * 3 + m) * 8 + (b & 7)) << 3) + (b >> 3);
                g_s[base + 0] = g.x;
                g_s[base + 2] = g.y;
                g_s[base + 4] = g.z;
                g_s[base + 6] = g.w;
            }
        }
        __syncthreads();

        #pragma unroll 2
        for (int j = 0; j < KC; j++) {
            // weights (stride-32 within warp -> conflict-free), packed {w, w}
            ull wv2[4];
            #pragma unroll
            for (int r = 0; r < 4; r++) {
                float w = w_s[j * VT + vth + 32 * r];
                wv2[r] = pk2(w, w);
            }
            // packed G rows: per row m, 2x LDS.128 -> {x0,x1},{y0,y1},{z0,z1},{w0,w1}
            const ulonglong2* gb =
                (const ulonglong2*)&g_s[((j * 3) * 8 + bth) << 3];
            #pragma unroll
            for (int m = 0; m < 3; m++) {
                ulonglong2 p0 = gb[m * 16 + 0];   // {xx, yy}
                ulonglong2 p1 = gb[m * 16 + 1];   // {zz, ww}
                #pragma unroll
                for (int r = 0; r < 4; r++) {
                    ull t = fma2(p1.x, qz2[r], p1.y);
                    t = fma2(p0.y, qy2[r], t);
                    t = fma2(p0.x, qx2[r], t);
                    acc[r][m] = fma2(wv2[r], t, acc[r][m]);
                }
            }
        }
    }

    // stores: coalesced scalar (lanes = consecutive v)
    #pragma unroll
    for (int r = 0; r < 4; r++) {
        int v = v0 + vth + 32 * r;
        if (v < NV) {
            float2 a0 = unpk2(acc[r][0]);
            float2 a1 = unpk2(acc[r][1]);
            float2 a2 = unpk2(acc[r][2]);
            int bA = b0 + bth;
            int bB = b0 + bth + 8;
            float* oA = out_V + ((size_t)bA * NV + v) * 3;
            float* oB = out_V + ((size_t)bB * NV + v) * 3;
            oA[0] = a0.x; oA[1] = a1.x; oA[2] = a2.x;
            oB[0] = a0.y; oB[1] = a1.y; oB[2] = a2.y;
        }
    }
}

// ---------------------------------------------------------------------------
extern "C" void kernel_launch(void* const* d_in, const int* in_sizes, int n_in,
                              void* d_out, int out_size) {
    const float* pose        = (const float*)d_in[0];
    const float* bone_len    = (const float*)d_in[1];
    const float* cbl         = (const float*)d_in[2];
    const float* trans       = (const float*)d_in[3];
    const float* scale       = (const float*)d_in[4];
    const float* v_template  = (const float*)d_in[5];
    const float* t_pose      = (const float*)d_in[6];
    const float* weights     = (const float*)d_in[7];
    const int*   parent      = (const int*)d_in[8];
    const int*   bone_mapper = (const int*)d_in[9];

    float* out   = (float*)d_out;
    float* out_V = out;                                  // [B, NV, 3]
    float* out_J = out + (size_t)BATCH * NV * 3;         // [B, NJ, 3]

    dim3 tb(32, 8);
    dim3 tg((NJ + 31) / 32, (VPAD + 31) / 32);
    transpose_w_kernel<<<tg, tb>>>(weights);

    skeleton_kernel<<<BATCH / 4, 128>>>(pose, bone_len, cbl, trans, scale,
                                        t_pose, parent, bone_mapper, out_J);

    dim3 sg((NV + VT - 1) / VT, BATCH / BT);
    skin_kernel<<<sg, 256>>>(v_template, out_V);
}

// round 5
// speedup vs baseline: 1.5984x; 1.5984x over previous
#include <cuda_runtime.h>
#include <math.h>
#include <stdint.h>

#define NJ 140
#define NV 13059
#define NB 28
#define BATCH 512
#define VPAD 13312        // 52 * 256
#define VT 256
#define BT 16
#define KC 28
#define NCH 5             // NJ / KC

// Scratch (device globals; no allocations allowed)
__device__ __align__(16) float g_G[BATCH * NJ * 12];   // folded matrices [b][j][3x4]
__device__ __align__(16) float g_Wt[NJ * VPAD];        // transposed weights [j][v], zero-pad

// ---- cp.async helpers -------------------------------------------------------
__device__ __forceinline__ void cpa16(uint32_t smem, const void* gmem) {
    asm volatile("cp.async.cg.shared.global [%0], [%1], 16;" :: "r"(smem), "l"(gmem));
}
__device__ __forceinline__ void cpa_commit() {
    asm volatile("cp.async.commit_group;" ::: "memory");
}
__device__ __forceinline__ void cpa_wait0() {
    asm volatile("cp.async.wait_group 0;" ::: "memory");
}

// ---------------------------------------------------------------------------
// Kernel 0: transpose weights (13059 x 140) -> (140 x VPAD), pad with zeros
// ---------------------------------------------------------------------------
__global__ void transpose_w_kernel(const float* __restrict__ W) {
    __shared__ float tile[32][33];
    int j0 = blockIdx.x * 32;
    int v0 = blockIdx.y * 32;
    int tx = threadIdx.x, ty = threadIdx.y;   // blockDim (32, 8)
    #pragma unroll
    for (int k = 0; k < 4; k++) {
        int v = v0 + ty + k * 8;
        int j = j0 + tx;
        float val = 0.f;
        if (v < NV && j < NJ) val = W[v * NJ + j];
        tile[ty + k * 8][tx] = val;
    }
    __syncthreads();
    #pragma unroll
    for (int k = 0; k < 4; k++) {
        int j = j0 + ty + k * 8;
        int v = v0 + tx;
        if (j < NJ && v < VPAD) g_Wt[j * VPAD + v] = tile[tx][ty + k * 8];
    }
}

// ---------------------------------------------------------------------------
// Kernel 1: per-batch skeleton. One warp per batch element.
// ---------------------------------------------------------------------------
__global__ void skeleton_kernel(const float* __restrict__ pose,
                                const float* __restrict__ bone_lengths,
                                const float* __restrict__ cbl,
                                const float* __restrict__ trans,
                                const float* __restrict__ scale,
                                const float* __restrict__ Jt,
                                const int*   __restrict__ parent,
                                const int*   __restrict__ bone_mapper,
                                float* __restrict__ out_J) {
    __shared__ float M[4][NJ * 12];
    __shared__ int par_s[NJ];
    int lane = threadIdx.x & 31;
    int w    = threadIdx.x >> 5;
    int b    = blockIdx.x * 4 + w;

    for (int i = threadIdx.x; i < NJ; i += 128) par_s[i] = parent[i];
    __syncthreads();

    float* Mw = M[w];

    // ---- Phase A: local transforms ----
    for (int j = lane; j < NJ; j += 32) {
        float z = pose[b * NJ * 3 + j * 3 + 0];
        float y = pose[b * NJ * 3 + j * 3 + 1];
        float x = pose[b * NJ * 3 + j * 3 + 2];
        float cx, sx, cy, sy, cz, sz;
        sincosf(x, &sx, &cx);
        sincosf(y, &sy, &cy);
        sincosf(z, &sz, &cz);
        float r00 = cz * cy, r01 = cz * sy * sx - sz * cx, r02 = cz * sy * cx + sz * sx;
        float r10 = sz * cy, r11 = sz * sy * sx + cz * cx, r12 = sz * sy * cx - cz * sx;
        float r20 = -sy,     r21 = cy * sx,                r22 = cy * cx;
        float t0, t1, t2;
        if (j == 0) {
            t0 = Jt[0]; t1 = Jt[1]; t2 = Jt[2];
        } else {
            int p = par_s[j];
            float ox = Jt[j * 3 + 0] - Jt[p * 3 + 0];
            float oy = Jt[j * 3 + 1] - Jt[p * 3 + 1];
            float oz = Jt[j * 3 + 2] - Jt[p * 3 + 2];
            float sc;
            if (j == 1) {
                sc = cbl[b];
            } else {
                int blid = bone_mapper[j];
                if (blid >= 0) {
                    float bv = bone_lengths[b * NB + blid];
                    sc = 2.f / (1.f + expf(-bv * 0.2f));   // 2*sigmoid(x/5)
                } else {
                    sc = 1.f;
                }
            }
            t0 = ox * sc; t1 = oy * sc; t2 = oz * sc;
        }
        float* d = Mw + j * 12;
        d[0] = r00; d[1] = r01; d[2]  = r02; d[3]  = t0;
        d[4] = r10; d[5] = r11; d[6]  = r12; d[7]  = t1;
        d[8] = r20; d[9] = r21; d[10] = r22; d[11] = t2;
    }
    __syncwarp();

    // ---- Phase B: serial kinematic chain ----
    int m = lane >> 2, n = lane & 3;
    for (int i = 1; i < NJ; i++) {
        int p = par_s[i];
        float val = 0.f;
        if (lane < 12) {
            float a0 = Mw[p * 12 + m * 4 + 0];
            float a1 = Mw[p * 12 + m * 4 + 1];
            float a2 = Mw[p * 12 + m * 4 + 2];
            float b0 = Mw[i * 12 + 0 + n];
            float b1 = Mw[i * 12 + 4 + n];
            float b2 = Mw[i * 12 + 8 + n];
            val = fmaf(a0, b0, fmaf(a1, b1, a2 * b2));
            if (n == 3) val += Mw[p * 12 + m * 4 + 3];
        }
        __syncwarp();
        if (lane < 12) Mw[i * 12 + lane] = val;
        __syncwarp();
    }

    // ---- Phase C: outputs ----
    float s   = scale[b];
    float trx = trans[b * 3 + 0];
    float try_ = trans[b * 3 + 1];
    float trz = trans[b * 3 + 2];
    for (int j = lane; j < NJ; j += 32) {
        const float* d = Mw + j * 12;
        float r00 = d[0], r01 = d[1], r02 = d[2],  t0 = d[3];
        float r10 = d[4], r11 = d[5], r12 = d[6],  t1 = d[7];
        float r20 = d[8], r21 = d[9], r22 = d[10], t2 = d[11];

        float* jo = out_J + ((size_t)b * NJ + j) * 3;
        jo[0] = fmaf(t0, s, trx);
        jo[1] = fmaf(t1, s, try_);
        jo[2] = fmaf(t2, s, trz);

        float jtx = Jt[j * 3 + 0], jty = Jt[j * 3 + 1], jtz = Jt[j * 3 + 2];
        float g0 = s * (t0 - (r00 * jtx + r01 * jty + r02 * jtz)) + trx;
        float g1 = s * (t1 - (r10 * jtx + r11 * jty + r12 * jtz)) + try_;
        float g2 = s * (t2 - (r20 * jtx + r21 * jty + r22 * jtz)) + trz;
        float* g = g_G + ((size_t)b * NJ + j) * 12;
        g[0] = s * r00; g[1] = s * r01; g[2]  = s * r02; g[3]  = g0;
        g[4] = s * r10; g[5] = s * r11; g[6]  = s * r12; g[7]  = g1;
        g[8] = s * r20; g[9] = s * r21; g[10] = s * r22; g[11] = g2;
    }
}

// ---------------------------------------------------------------------------
// Kernel 2: skinning. Block = 256 threads, tile = 256 vertices x 16 batches.
// Thread = 8 vertices x 2 batches x 3 accumulators. cp.async double-buffered
// staging of weights + G chunks (KC=28 joints per chunk, 5 chunks).
// ---------------------------------------------------------------------------
__global__ void __launch_bounds__(256, 2) skin_kernel(const float* __restrict__ vtemp,
                                                      float* __restrict__ out_V) {
    extern __shared__ __align__(16) float smem[];
    // layout: w_s[2][KC*VT] then g_s[2][BT*KC*12]
    float* w_sb = smem;                       // 2 * 7168 floats
    float* g_sb = smem + 2 * KC * VT;         // 2 * 5376 floats

    int tx  = threadIdx.x;
    int vth = tx & 31;
    int bth = tx >> 5;               // 0..7 : batch pair (b0+bth, b0+bth+8)
    int v0  = blockIdx.x * VT;
    int b0  = blockIdx.y * BT;

    uint32_t w_sb_u = (uint32_t)__cvta_generic_to_shared(w_sb);
    uint32_t g_sb_u = (uint32_t)__cvta_generic_to_shared(g_sb);

    // ---- staging lambda (cp.async), chunk k-index c into buffer buf ----
    auto stage = [&](int c, int buf) {
        int k0 = c * KC;
        // weights: KC*VT/4 = 1792 float4, 7 per thread
        const float* wsrc = g_Wt + (size_t)k0 * VPAD + v0;
        uint32_t wdst = w_sb_u + (uint32_t)(buf * (KC * VT) * 4);
        #pragma unroll
        for (int i = 0; i < 7; i++) {
            int idx4 = tx + i * 256;          // < 1792
            int j  = idx4 >> 6;               // /64
            int vl = idx4 & 63;
            cpa16(wdst + (uint32_t)((j * VT + vl * 4) * 4),
                  wsrc + (size_t)j * VPAD + vl * 4);
        }
        // G: BT*KC*3 = 1344 float4, 6 per thread (last partial)
        const float4* gsrc = (const float4*)g_G;
        uint32_t gdst = g_sb_u + (uint32_t)(buf * (BT * KC * 12) * 4);
        #pragma unroll
        for (int i = 0; i < 6; i++) {
            int idx4 = tx + i * 256;
            if (idx4 < BT * KC * 3) {
                int b   = idx4 / (KC * 3);
                int rem = idx4 - b * (KC * 3);      // j*3+m
                cpa16(gdst + (uint32_t)((b * (KC * 3) + rem) * 16),
                      gsrc + (size_t)(b0 + b) * (NJ * 3) + (size_t)k0 * 3 + rem);
            }
        }
        cpa_commit();
    };

    // q vectors
    float qx[8], qy[8], qz[8];
    #pragma unroll
    for (int r = 0; r < 8; r++) {
        int v = v0 + vth + 32 * r;
        if (v < NV) {
            qx[r] = vtemp[v * 3 + 0];
            qy[r] = vtemp[v * 3 + 1];
            qz[r] = vtemp[v * 3 + 2];
        } else {
            qx[r] = qy[r] = qz[r] = 0.f;
        }
    }

    float acc[2][8][3];
    #pragma unroll
    for (int s = 0; s < 2; s++)
        #pragma unroll
        for (int r = 0; r < 8; r++)
            acc[s][r][0] = acc[s][r][1] = acc[s][r][2] = 0.f;

    stage(0, 0);
    cpa_wait0();
    __syncthreads();

    for (int c = 0; c < NCH; c++) {
        int buf = c & 1;
        if (c + 1 < NCH) stage(c + 1, buf ^ 1);

        const float* w_s = w_sb + buf * (KC * VT);
        const float* g_s = g_sb + buf * (BT * KC * 12);

        #pragma unroll 2
        for (int j = 0; j < KC; j++) {
            float wv[8];
            #pragma unroll
            for (int r = 0; r < 8; r++) wv[r] = w_s[j * VT + vth + 32 * r];
            #pragma unroll
            for (int s = 0; s < 2; s++) {
                int bl = bth + 8 * s;
                const float4* gp = (const float4*)&g_s[(bl * KC + j) * 12];
                float4 G0 = gp[0];
                float4 G1 = gp[1];
                float4 G2 = gp[2];
                #pragma unroll
                for (int r = 0; r < 8; r++) {
                    float t0 = fmaf(G0.x, qx[r], fmaf(G0.y, qy[r], fmaf(G0.z, qz[r], G0.w)));
                    float t1 = fmaf(G1.x, qx[r], fmaf(G1.y, qy[r], fmaf(G1.z, qz[r], G1.w)));
                    float t2 = fmaf(G2.x, qx[r], fmaf(G2.y, qy[r], fmaf(G2.z, qz[r], G2.w)));
                    acc[s][r][0] = fmaf(wv[r], t0, acc[s][r][0]);
                    acc[s][r][1] = fmaf(wv[r], t1, acc[s][r][1]);
                    acc[s][r][2] = fmaf(wv[r], t2, acc[s][r][2]);
                }
            }
        }

        if (c + 1 < NCH) cpa_wait0();
        __syncthreads();
    }

    #pragma unroll
    for (int s = 0; s < 2; s++) {
        int b = b0 + bth + 8 * s;
        #pragma unroll
        for (int r = 0; r < 8; r++) {
            int v = v0 + vth + 32 * r;
            if (v < NV) {
                float* o = out_V + ((size_t)b * NV + v) * 3;
                o[0] = acc[s][r][0];
                o[1] = acc[s][r][1];
                o[2] = acc[s][r][2];
            }
        }
    }
}

// ---------------------------------------------------------------------------
extern "C" void kernel_launch(void* const* d_in, const int* in_sizes, int n_in,
                              void* d_out, int out_size) {
    const float* pose        = (const float*)d_in[0];
    const float* bone_len    = (const float*)d_in[1];
    const float* cbl         = (const float*)d_in[2];
    const float* trans       = (const float*)d_in[3];
    const float* scale       = (const float*)d_in[4];
    const float* v_template  = (const float*)d_in[5];
    const float* t_pose      = (const float*)d_in[6];
    const float* weights     = (const float*)d_in[7];
    const int*   parent      = (const int*)d_in[8];
    const int*   bone_mapper = (const int*)d_in[9];

    float* out   = (float*)d_out;
    float* out_V = out;                                  // [B, NV, 3]
    float* out_J = out + (size_t)BATCH * NV * 3;         // [B, NJ, 3]

    dim3 tb(32, 8);
    dim3 tg((NJ + 31) / 32, (VPAD + 31) / 32);
    transpose_w_kernel<<<tg, tb>>>(weights);

    skeleton_kernel<<<BATCH / 4, 128>>>(pose, bone_len, cbl, trans, scale,
                                        t_pose, parent, bone_mapper, out_J);

    const int smem_bytes = (2 * KC * VT + 2 * BT * KC * 12) * 4;   // 100352
    static int configured = -1;
    if (configured != smem_bytes) {
        cudaFuncSetAttribute(skin_kernel, cudaFuncAttributeMaxDynamicSharedMemorySize,
                             smem_bytes);
        configured = smem_bytes;
    }
    dim3 sg((NV + VT - 1) / VT, BATCH / BT);
    skin_kernel<<<sg, 256, smem_bytes>>>(v_template, out_V);
}

// round 14
// speedup vs baseline: 1.7072x; 1.0681x over previous
#include <cuda_runtime.h>
#include <cuda_bf16.h>
#include <math.h>
#include <stdint.h>

#define NJ 140
#define NV 13059
#define NB 28
#define BATCH 512

#define KREG 576          // 560 (j,n) padded to 9*64
#define KTOT 1728         // 3 regions: AhBh | AhBl | AlBh
#define NCHUNK 27         // KTOT / 64
#define NTOT 1536         // 512 b * 3 m, packed n = b*3+m
#define NT_CTA 96         // N per CTA = 32 batches * 3
#define MT_CTA 128        // M per CTA (vertices)

// dynamic smem byte offsets
#define SO_W 0
#define W_STRIDE 145          // 140 cols + pad
#define SO_A0 74752           // 128 x 64 bf16, SW128 (16384 B)
#define SO_A1 91136
#define SO_B0 107520          // 96 x 64 bf16, SW128 (12288 B)
#define SO_B1 119808
#define SMEM_BYTES 132096
#define EP_STRIDE 98          // epilogue fp32 tile reuses w region

// Scratch (device globals; no allocations allowed)
__device__ __align__(16) float g_G[BATCH * NJ * 12];              // folded matrices [b][j][3x4]
__device__ __align__(16) __nv_bfloat16 g_B[(size_t)NTOT * KTOT];  // packed B' [n][k]

// ---- PTX helpers (all baseline sm_80/90 features, no 'a' suffix) ----------
__device__ __forceinline__ void cpa16(uint32_t smem, const void* gmem) {
    asm volatile("cp.async.cg.shared.global [%0], [%1], 16;" :: "r"(smem), "l"(gmem));
}
__device__ __forceinline__ void cpa_commit() {
    asm volatile("cp.async.commit_group;" ::: "memory");
}
__device__ __forceinline__ void cpa_wait0() {
    asm volatile("cp.async.wait_group 0;" ::: "memory");
}
__device__ __forceinline__ void ldsm_x4(uint32_t addr, uint32_t* r) {
    asm volatile("ldmatrix.sync.aligned.m8n8.x4.shared.b16 {%0,%1,%2,%3}, [%4];"
                 : "=r"(r[0]), "=r"(r[1]), "=r"(r[2]), "=r"(r[3]) : "r"(addr));
}
__device__ __forceinline__ void mma16816(float* c, const uint32_t* a, const uint32_t* b) {
    asm volatile("mma.sync.aligned.m16n8k16.row.col.f32.bf16.bf16.f32 "
                 "{%0,%1,%2,%3}, {%4,%5,%6,%7}, {%8,%9}, {%0,%1,%2,%3};"
                 : "+f"(c[0]), "+f"(c[1]), "+f"(c[2]), "+f"(c[3])
                 : "r"(a[0]), "r"(a[1]), "r"(a[2]), "r"(a[3]), "r"(b[0]), "r"(b[1]));
}

// ---------------------------------------------------------------------------
// Kernel 1: per-batch skeleton. One warp per batch element. (validated)
// ---------------------------------------------------------------------------
__global__ void skeleton_kernel(const float* __restrict__ pose,
                                const float* __restrict__ bone_lengths,
                                const float* __restrict__ cbl,
                                const float* __restrict__ trans,
                                const float* __restrict__ scale,
                                const float* __restrict__ Jt,
                                const int*   __restrict__ parent,
                                const int*   __restrict__ bone_mapper,
                                float* __restrict__ out_J) {
    __shared__ float M[4][NJ * 12];
    __shared__ int par_s[NJ];
    int lane = threadIdx.x & 31;
    int w    = threadIdx.x >> 5;
    int b    = blockIdx.x * 4 + w;

    for (int i = threadIdx.x; i < NJ; i += 128) par_s[i] = parent[i];
    __syncthreads();

    float* Mw = M[w];

    for (int j = lane; j < NJ; j += 32) {
        float z = pose[b * NJ * 3 + j * 3 + 0];
        float y = pose[b * NJ * 3 + j * 3 + 1];
        float x = pose[b * NJ * 3 + j * 3 + 2];
        float cx, sx, cy, sy, cz, sz;
        sincosf(x, &sx, &cx);
        sincosf(y, &sy, &cy);
        sincosf(z, &sz, &cz);
        float r00 = cz * cy, r01 = cz * sy * sx - sz * cx, r02 = cz * sy * cx + sz * sx;
        float r10 = sz * cy, r11 = sz * sy * sx + cz * cx, r12 = sz * sy * cx - cz * sx;
        float r20 = -sy,     r21 = cy * sx,                r22 = cy * cx;
        float t0, t1, t2;
        if (j == 0) {
            t0 = Jt[0]; t1 = Jt[1]; t2 = Jt[2];
        } else {
            int p = par_s[j];
            float ox = Jt[j * 3 + 0] - Jt[p * 3 + 0];
            float oy = Jt[j * 3 + 1] - Jt[p * 3 + 1];
            float oz = Jt[j * 3 + 2] - Jt[p * 3 + 2];
            float sc;
            if (j == 1) {
                sc = cbl[b];
            } else {
                int blid = bone_mapper[j];
                if (blid >= 0) {
                    float bv = bone_lengths[b * NB + blid];
                    sc = 2.f / (1.f + expf(-bv * 0.2f));
                } else {
                    sc = 1.f;
                }
            }
            t0 = ox * sc; t1 = oy * sc; t2 = oz * sc;
        }
        float* d = Mw + j * 12;
        d[0] = r00; d[1] = r01; d[2]  = r02; d[3]  = t0;
        d[4] = r10; d[5] = r11; d[6]  = r12; d[7]  = t1;
        d[8] = r20; d[9] = r21; d[10] = r22; d[11] = t2;
    }
    __syncwarp();

    int m = lane >> 2, n = lane & 3;
    for (int i = 1; i < NJ; i++) {
        int p = par_s[i];
        float val = 0.f;
        if (lane < 12) {
            float a0 = Mw[p * 12 + m * 4 + 0];
            float a1 = Mw[p * 12 + m * 4 + 1];
            float a2 = Mw[p * 12 + m * 4 + 2];
            float b0 = Mw[i * 12 + 0 + n];
            float b1 = Mw[i * 12 + 4 + n];
            float b2 = Mw[i * 12 + 8 + n];
            val = fmaf(a0, b0, fmaf(a1, b1, a2 * b2));
            if (n == 3) val += Mw[p * 12 + m * 4 + 3];
        }
        __syncwarp();
        if (lane < 12) Mw[i * 12 + lane] = val;
        __syncwarp();
    }

    float s   = scale[b];
    float trx = trans[b * 3 + 0];
    float try_ = trans[b * 3 + 1];
    float trz = trans[b * 3 + 2];
    for (int j = lane; j < NJ; j += 32) {
        const float* d = Mw + j * 12;
        float r00 = d[0], r01 = d[1], r02 = d[2],  t0 = d[3];
        float r10 = d[4], r11 = d[5], r12 = d[6],  t1 = d[7];
        float r20 = d[8], r21 = d[9], r22 = d[10], t2 = d[11];

        float* jo = out_J + ((size_t)b * NJ + j) * 3;
        jo[0] = fmaf(t0, s, trx);
        jo[1] = fmaf(t1, s, try_);
        jo[2] = fmaf(t2, s, trz);

        float jtx = Jt[j * 3 + 0], jty = Jt[j * 3 + 1], jtz = Jt[j * 3 + 2];
        float g0 = s * (t0 - (r00 * jtx + r01 * jty + r02 * jtz)) + trx;
        float g1 = s * (t1 - (r10 * jtx + r11 * jty + r12 * jtz)) + try_;
        float g2 = s * (t2 - (r20 * jtx + r21 * jty + r22 * jtz)) + trz;
        float* g = g_G + ((size_t)b * NJ + j) * 12;
        g[0] = s * r00; g[1] = s * r01; g[2]  = s * r02; g[3]  = g0;
        g[4] = s * r10; g[5] = s * r11; g[6]  = s * r12; g[7]  = g1;
        g[8] = s * r20; g[9] = s * r21; g[10] = s * r22; g[11] = g2;
    }
}

// ---------------------------------------------------------------------------
// Kernel 2: pack B'[n][k] bf16. n = b*3+m, k = region*576 + (j*4+nn).
// region 0: hi(G), region 1: lo(G), region 2: hi(G). Pads are zero.
// ---------------------------------------------------------------------------
__global__ void pack_B_kernel() {
    int idx = blockIdx.x * 256 + threadIdx.x;           // pair index
    const int pairs_per_row = KTOT / 2;                 // 864
    if (idx >= NTOT * pairs_per_row) return;
    int n  = idx / pairs_per_row;
    int kp = idx - n * pairs_per_row;
    int k  = kp * 2;
    int r  = k / KREG;
    int jn = k - r * KREG;
    float x0 = 0.f, x1 = 0.f;
    if (jn < NJ * 4) {
        int j  = jn >> 2;
        int nn = jn & 3;                                // 0 or 2 (k even)
        int bb = n / 3;
        int mm = n - bb * 3;
        const float* gp = g_G + ((size_t)(bb * NJ + j)) * 12 + mm * 4 + nn;
        x0 = gp[0];
        x1 = gp[1];
    }
    __nv_bfloat162 h = __float22bfloat162_rn(make_float2(x0, x1));
    __nv_bfloat162 outv;
    if (r == 1) {
        float l0 = x0 - __low2float(h);
        float l1 = x1 - __high2float(h);
        outv = __float22bfloat162_rn(make_float2(l0, l1));
    } else {
        outv = h;
    }
    *(__nv_bfloat162*)(g_B + (size_t)n * KTOT + k) = outv;
}

// ---------------------------------------------------------------------------
// Kernel 3: skinning GEMM via mma.sync bf16. CTA = 128 v x 96 n, 8 warps
// (warp tile 32 x 48). A built on-the-fly from w & q; B cp.async staged.
// ---------------------------------------------------------------------------
__global__ void __launch_bounds__(256, 1) skin_mma_kernel(const float* __restrict__ vtemp,
                                                          const float* __restrict__ weights,
                                                          float* __restrict__ out_V) {
    extern __shared__ __align__(16) char smem[];
    uint32_t sbase = (uint32_t)__cvta_generic_to_shared(smem);
    float* w_s = (float*)(smem + SO_W);

    int tid  = threadIdx.x;
    int wid  = tid >> 5;
    int lane = tid & 31;
    int wm   = wid & 3;               // warp m-tile: rows [wm*32, +32)
    int wn   = wid >> 2;              // warp n-tile: cols [wn*48, +48)
    int v0   = blockIdx.x * MT_CTA;
    int n0   = blockIdx.y * NT_CTA;
    int b0   = blockIdx.y * 32;

    // load w tile into SMEM: w_s[v*145 + j], zero pad j>=140 / v OOB
    for (int idx = tid; idx < 128 * W_STRIDE; idx += 256) {
        int v = idx / W_STRIDE;
        int j = idx - v * W_STRIDE;
        float val = 0.f;
        if (j < NJ && (v0 + v) < NV) val = weights[(size_t)(v0 + v) * NJ + j];
        w_s[idx] = val;
    }

    // per-thread A-build coordinates
    int e  = lane & 7;
    int ip = lane >> 3;                 // 0..3
    int vA = wid * 16 + e;
    int vB = wid * 16 + 8 + e;
    float qA[3] = {0.f, 0.f, 0.f}, qB[3] = {0.f, 0.f, 0.f};
    if (v0 + vA < NV) {
        qA[0] = vtemp[(v0 + vA) * 3 + 0];
        qA[1] = vtemp[(v0 + vA) * 3 + 1];
        qA[2] = vtemp[(v0 + vA) * 3 + 2];
    }
    if (v0 + vB < NV) {
        qB[0] = vtemp[(v0 + vB) * 3 + 0];
        qB[1] = vtemp[(v0 + vB) * 3 + 1];
        qB[2] = vtemp[(v0 + vB) * 3 + 2];
    }

    const uint32_t a_off[2] = {SO_A0, SO_A1};
    const uint32_t b_off[2] = {SO_B0, SO_B1};

    // ---- B staging via cp.async (SW128 swizzled) ----
    auto stageB = [&](int c, int buf) {
        uint32_t bdst = sbase + b_off[buf];
        const char* src0 = (const char*)g_B + (size_t)2 * ((size_t)n0 * KTOT + c * 64);
        #pragma unroll
        for (int i = 0; i < 3; i++) {
            int idx = tid + i * 256;            // < 768 = 96 rows * 8 chunks
            int row = idx >> 3;
            int g   = idx & 7;
            uint32_t off = (uint32_t)(row * 128 + g * 16);
            uint32_t swz = off ^ ((off >> 3) & 0x70);
            cpa16(bdst + swz, src0 + (size_t)row * (KTOT * 2) + g * 16);
        }
        cpa_commit();
    };

    // ---- A tile build from w & q (SW128 swizzled bf16x2 writes) ----
    auto buildA = [&](int c, int buf) {
        char* adst = smem + a_off[buf];
        int r  = c / 9;
        int cc = c - 9 * r;
        bool lo = (r == 2);
        #pragma unroll
        for (int vs = 0; vs < 2; vs++) {
            int v = vs ? vB : vA;
            const float* q = vs ? qB : qA;
            const float* wrow = w_s + v * W_STRIDE;
            uint32_t vx = (uint32_t)((v & 7) << 4);
            uint32_t vbase = (uint32_t)(v * 128);
            #pragma unroll
            for (int ti = 0; ti < 8; ti++) {
                int tp = ip + 4 * ti;                    // 0..31 (bf16 pair index)
                int j  = cc * 16 + (tp >> 1);            // < 144 (pad rows are 0)
                float wv = wrow[j];
                float p0, p1;
                if (tp & 1) { p0 = wv * q[2]; p1 = wv; }         // (qz, 1)
                else        { p0 = wv * q[0]; p1 = wv * q[1]; }  // (qx, qy)
                __nv_bfloat162 h = __float22bfloat162_rn(make_float2(p0, p1));
                __nv_bfloat162 val;
                if (lo) {
                    float l0 = p0 - __low2float(h);
                    float l1 = p1 - __high2float(h);
                    val = __float22bfloat162_rn(make_float2(l0, l1));
                } else {
                    val = h;
                }
                uint32_t boff = vbase + (((uint32_t)(tp * 4)) ^ vx);
                *(__nv_bfloat162*)(adst + boff) = val;
            }
        }
    };

    float acc[2][6][4];
    #pragma unroll
    for (int fm = 0; fm < 2; fm++)
        #pragma unroll
        for (int fn = 0; fn < 6; fn++)
            acc[fm][fn][0] = acc[fm][fn][1] = acc[fm][fn][2] = acc[fm][fn][3] = 0.f;

    // prologue
    stageB(0, 0);
    __syncthreads();          // w_s ready before buildA
    buildA(0, 0);
    cpa_wait0();
    __syncthreads();

    for (int c = 0; c < NCHUNK; c++) {
        int buf = c & 1;
        if (c + 1 < NCHUNK) {
            stageB(c + 1, buf ^ 1);
            buildA(c + 1, buf ^ 1);
        }

        uint32_t aBase = sbase + a_off[buf];
        uint32_t bBase = sbase + b_off[buf];

        #pragma unroll
        for (int ks = 0; ks < 4; ks++) {
            uint32_t afr[2][4];
            #pragma unroll
            for (int fm = 0; fm < 2; fm++) {
                int row = wm * 32 + fm * 16 + (lane & 15);
                uint32_t kb = (uint32_t)(ks * 32 + ((lane >> 4) << 4));
                uint32_t addr = aBase + (uint32_t)(row * 128) + (kb ^ (uint32_t)((row & 7) << 4));
                ldsm_x4(addr, afr[fm]);
            }
            uint32_t bfr[6][2];
            #pragma unroll
            for (int fp = 0; fp < 3; fp++) {
                int mi = lane >> 3;
                int nrow = wn * 48 + fp * 16 + ((mi >> 1) << 3) + (lane & 7);
                uint32_t kb = (uint32_t)(ks * 32 + ((mi & 1) << 4));
                uint32_t addr = bBase + (uint32_t)(nrow * 128) + (kb ^ (uint32_t)((nrow & 7) << 4));
                uint32_t rb[4];
                ldsm_x4(addr, rb);
                bfr[2 * fp][0]     = rb[0];
                bfr[2 * fp][1]     = rb[1];
                bfr[2 * fp + 1][0] = rb[2];
                bfr[2 * fp + 1][1] = rb[3];
            }
            #pragma unroll
            for (int fm = 0; fm < 2; fm++)
                #pragma unroll
                for (int fn = 0; fn < 6; fn++)
                    mma16816(acc[fm][fn], afr[fm], bfr[fn]);
        }

        if (c + 1 < NCHUNK) cpa_wait0();
        __syncthreads();
    }

    // ---- epilogue: acc -> SMEM fp32 tile (reuses w region) -> global ----
    float* ep = (float*)smem;
    #pragma unroll
    for (int fm = 0; fm < 2; fm++) {
        #pragma unroll
        for (int fn = 0; fn < 6; fn++) {
            int v = wm * 32 + fm * 16 + (lane >> 2);
            int n = wn * 48 + fn * 8 + ((lane & 3) << 1);
            *(float2*)&ep[v * EP_STRIDE + n] = make_float2(acc[fm][fn][0], acc[fm][fn][1]);
            *(float2*)&ep[(v + 8) * EP_STRIDE + n] = make_float2(acc[fm][fn][2], acc[fm][fn][3]);
        }
    }
    __syncthreads();

    int vv = tid & 127;
    int bh = tid >> 7;
    if (v0 + vv < NV) {
        const float* row = ep + vv * EP_STRIDE;
        #pragma unroll
        for (int i = 0; i < 16; i++) {
            int bl = bh * 16 + i;
            int bg = b0 + bl;
            float f0 = row[bl * 3 + 0];
            float f1 = row[bl * 3 + 1];
            float f2 = row[bl * 3 + 2];
            float* o = out_V + ((size_t)bg * NV + (v0 + vv)) * 3;
            o[0] = f0; o[1] = f1; o[2] = f2;
        }
    }
}

// ---------------------------------------------------------------------------
extern "C" void kernel_launch(void* const* d_in, const int* in_sizes, int n_in,
                              void* d_out, int out_size) {
    const float* pose        = (const float*)d_in[0];
    const float* bone_len    = (const float*)d_in[1];
    const float* cbl         = (const float*)d_in[2];
    const float* trans       = (const float*)d_in[3];
    const float* scale       = (const float*)d_in[4];
    const float* v_template  = (const float*)d_in[5];
    const float* t_pose      = (const float*)d_in[6];
    const float* weights     = (const float*)d_in[7];
    const int*   parent      = (const int*)d_in[8];
    const int*   bone_mapper = (const int*)d_in[9];

    float* out   = (float*)d_out;
    float* out_V = out;                                  // [B, NV, 3]
    float* out_J = out + (size_t)BATCH * NV * 3;         // [B, NJ, 3]

    skeleton_kernel<<<BATCH / 4, 128>>>(pose, bone_len, cbl, trans, scale,
                                        t_pose, parent, bone_mapper, out_J);

    {
        int pairs = NTOT * (KTOT / 2);
        pack_B_kernel<<<(pairs + 255) / 256, 256>>>();
    }

    static int configured = 0;
    if (!configured) {
        cudaFuncSetAttribute(skin_mma_kernel,
                             cudaFuncAttributeMaxDynamicSharedMemorySize, SMEM_BYTES);
        configured = 1;
    }
    dim3 sg((NV + MT_CTA - 1) / MT_CTA, NTOT / NT_CTA);
    skin_mma_kernel<<<sg, 256, SMEM_BYTES>>>(v_template, weights, out_V);
}

// round 16
// speedup vs baseline: 3.1221x; 1.8288x over previous
#include <cuda_runtime.h>
#include <cuda_bf16.h>
#include <math.h>
#include <stdint.h>

#define NJ 140
#define NV 13059
#define NB 28
#define BATCH 512

#define KREG 576          // 560 (j,n) padded to 9*64
#define KTOT 1728         // 3 regions: AhBh | AhBl | AlBh
#define NCHUNK 27         // KTOT / 64
#define NTOT 1536         // 512 b * 3 m, packed n = b*3+m
#define NT_CTA 96         // N per CTA = 32 batches * 3
#define MT_CTA 128        // M per CTA (vertices)
#define VPADA 13184       // 103 * 128

// dynamic smem byte offsets (GEMM kernel)
#define SO_A0 0               // 128 x 64 bf16, SW128 (16384 B)
#define SO_A1 16384
#define SO_B0 32768           // 96 x 64 bf16, SW128 (12288 B)
#define SO_B1 45056
#define SMEM_BYTES 57344
#define EP_STRIDE 98          // epilogue fp32 tile reuses smem base (128*98*4 = 50176 B)

// Scratch (device globals; no allocations allowed; zero-initialized)
__device__ __align__(16) float g_G[BATCH * NJ * 12];                  // folded matrices
__device__ __align__(16) __nv_bfloat16 g_B[(size_t)NTOT * KTOT];      // packed B' [n][k]
__device__ __align__(16) __nv_bfloat16 g_A[(size_t)VPADA * 2 * KREG]; // packed A [v][Ah(576)|Al(576)]

// ---- PTX helpers (baseline features only; no 'a'-suffix instructions) -----
__device__ __forceinline__ void cpa16(uint32_t smem, const void* gmem) {
    asm volatile("cp.async.cg.shared.global [%0], [%1], 16;" :: "r"(smem), "l"(gmem));
}
__device__ __forceinline__ void cpa_commit() {
    asm volatile("cp.async.commit_group;" ::: "memory");
}
__device__ __forceinline__ void cpa_wait0() {
    asm volatile("cp.async.wait_group 0;" ::: "memory");
}
__device__ __forceinline__ void ldsm_x4(uint32_t addr, uint32_t* r) {
    asm volatile("ldmatrix.sync.aligned.m8n8.x4.shared.b16 {%0,%1,%2,%3}, [%4];"
                 : "=r"(r[0]), "=r"(r[1]), "=r"(r[2]), "=r"(r[3]) : "r"(addr));
}
__device__ __forceinline__ void mma16816(float* c, const uint32_t* a, const uint32_t* b) {
    asm volatile("mma.sync.aligned.m16n8k16.row.col.f32.bf16.bf16.f32 "
                 "{%0,%1,%2,%3}, {%4,%5,%6,%7}, {%8,%9}, {%0,%1,%2,%3};"
                 : "+f"(c[0]), "+f"(c[1]), "+f"(c[2]), "+f"(c[3])
                 : "r"(a[0]), "r"(a[1]), "r"(a[2]), "r"(a[3]), "r"(b[0]), "r"(b[1]));
}

// ---------------------------------------------------------------------------
// Kernel 1: per-batch skeleton. One warp per batch element. (validated)
// ---------------------------------------------------------------------------
__global__ void skeleton_kernel(const float* __restrict__ pose,
                                const float* __restrict__ bone_lengths,
                                const float* __restrict__ cbl,
                                const float* __restrict__ trans,
                                const float* __restrict__ scale,
                                const float* __restrict__ Jt,
                                const int*   __restrict__ parent,
                                const int*   __restrict__ bone_mapper,
                                float* __restrict__ out_J) {
    __shared__ float M[4][NJ * 12];
    __shared__ int par_s[NJ];
    int lane = threadIdx.x & 31;
    int w    = threadIdx.x >> 5;
    int b    = blockIdx.x * 4 + w;

    for (int i = threadIdx.x; i < NJ; i += 128) par_s[i] = parent[i];
    __syncthreads();

    float* Mw = M[w];

    for (int j = lane; j < NJ; j += 32) {
        float z = pose[b * NJ * 3 + j * 3 + 0];
        float y = pose[b * NJ * 3 + j * 3 + 1];
        float x = pose[b * NJ * 3 + j * 3 + 2];
        float cx, sx, cy, sy, cz, sz;
        sincosf(x, &sx, &cx);
        sincosf(y, &sy, &cy);
        sincosf(z, &sz, &cz);
        float r00 = cz * cy, r01 = cz * sy * sx - sz * cx, r02 = cz * sy * cx + sz * sx;
        float r10 = sz * cy, r11 = sz * sy * sx + cz * cx, r12 = sz * sy * cx - cz * sx;
        float r20 = -sy,     r21 = cy * sx,                r22 = cy * cx;
        float t0, t1, t2;
        if (j == 0) {
            t0 = Jt[0]; t1 = Jt[1]; t2 = Jt[2];
        } else {
            int p = par_s[j];
            float ox = Jt[j * 3 + 0] - Jt[p * 3 + 0];
            float oy = Jt[j * 3 + 1] - Jt[p * 3 + 1];
            float oz = Jt[j * 3 + 2] - Jt[p * 3 + 2];
            float sc;
            if (j == 1) {
                sc = cbl[b];
            } else {
                int blid = bone_mapper[j];
                if (blid >= 0) {
                    float bv = bone_lengths[b * NB + blid];
                    sc = 2.f / (1.f + expf(-bv * 0.2f));
                } else {
                    sc = 1.f;
                }
            }
            t0 = ox * sc; t1 = oy * sc; t2 = oz * sc;
        }
        float* d = Mw + j * 12;
        d[0] = r00; d[1] = r01; d[2]  = r02; d[3]  = t0;
        d[4] = r10; d[5] = r11; d[6]  = r12; d[7]  = t1;
        d[8] = r20; d[9] = r21; d[10] = r22; d[11] = t2;
    }
    __syncwarp();

    int m = lane >> 2, n = lane & 3;
    for (int i = 1; i < NJ; i++) {
        int p = par_s[i];
        float val = 0.f;
        if (lane < 12) {
            float a0 = Mw[p * 12 + m * 4 + 0];
            float a1 = Mw[p * 12 + m * 4 + 1];
            float a2 = Mw[p * 12 + m * 4 + 2];
            float b0 = Mw[i * 12 + 0 + n];
            float b1 = Mw[i * 12 + 4 + n];
            float b2 = Mw[i * 12 + 8 + n];
            val = fmaf(a0, b0, fmaf(a1, b1, a2 * b2));
            if (n == 3) val += Mw[p * 12 + m * 4 + 3];
        }
        __syncwarp();
        if (lane < 12) Mw[i * 12 + lane] = val;
        __syncwarp();
    }

    float s   = scale[b];
    float trx = trans[b * 3 + 0];
    float try_ = trans[b * 3 + 1];
    float trz = trans[b * 3 + 2];
    for (int j = lane; j < NJ; j += 32) {
        const float* d = Mw + j * 12;
        float r00 = d[0], r01 = d[1], r02 = d[2],  t0 = d[3];
        float r10 = d[4], r11 = d[5], r12 = d[6],  t1 = d[7];
        float r20 = d[8], r21 = d[9], r22 = d[10], t2 = d[11];

        float* jo = out_J + ((size_t)b * NJ + j) * 3;
        jo[0] = fmaf(t0, s, trx);
        jo[1] = fmaf(t1, s, try_);
        jo[2] = fmaf(t2, s, trz);

        float jtx = Jt[j * 3 + 0], jty = Jt[j * 3 + 1], jtz = Jt[j * 3 + 2];
        float g0 = s * (t0 - (r00 * jtx + r01 * jty + r02 * jtz)) + trx;
        float g1 = s * (t1 - (r10 * jtx + r11 * jty + r12 * jtz)) + try_;
        float g2 = s * (t2 - (r20 * jtx + r21 * jty + r22 * jtz)) + trz;
        float* g = g_G + ((size_t)b * NJ + j) * 12;
        g[0] = s * r00; g[1] = s * r01; g[2]  = s * r02; g[3]  = g0;
        g[4] = s * r10; g[5] = s * r11; g[6]  = s * r12; g[7]  = g1;
        g[8] = s * r20; g[9] = s * r21; g[10] = s * r22; g[11] = g2;
    }
}

// ---------------------------------------------------------------------------
// Kernel 2: pack B'[n][k] bf16. n = b*3+m, k = region*576 + (j*4+nn).
// region 0: hi(G), region 1: lo(G), region 2: hi(G). Pads are zero.
// ---------------------------------------------------------------------------
__global__ void pack_B_kernel() {
    int idx = blockIdx.x * 256 + threadIdx.x;           // pair index
    const int pairs_per_row = KTOT / 2;                 // 864
    if (idx >= NTOT * pairs_per_row) return;
    int n  = idx / pairs_per_row;
    int kp = idx - n * pairs_per_row;
    int k  = kp * 2;
    int r  = k / KREG;
    int jn = k - r * KREG;
    float x0 = 0.f, x1 = 0.f;
    if (jn < NJ * 4) {
        int j  = jn >> 2;
        int nn = jn & 3;                                // 0 or 2 (k even)
        int bb = n / 3;
        int mm = n - bb * 3;
        const float* gp = g_G + ((size_t)(bb * NJ + j)) * 12 + mm * 4 + nn;
        x0 = gp[0];
        x1 = gp[1];
    }
    __nv_bfloat162 h = __float22bfloat162_rn(make_float2(x0, x1));
    __nv_bfloat162 outv;
    if (r == 1) {
        float l0 = x0 - __low2float(h);
        float l1 = x1 - __high2float(h);
        outv = __float22bfloat162_rn(make_float2(l0, l1));
    } else {
        outv = h;
    }
    *(__nv_bfloat162*)(g_B + (size_t)n * KTOT + k) = outv;
}

// ---------------------------------------------------------------------------
// Kernel 2b: pack A[v][k'] bf16, k' in [0,1152): Ah (576) then Al (576).
// A[v][j*4+nn] = w[v][j] * {qx,qy,qz,1}[nn]. j >= NJ pads are zero.
// ---------------------------------------------------------------------------
__global__ void pack_A_kernel(const float* __restrict__ vtemp,
                              const float* __restrict__ weights) {
    int idx = blockIdx.x * 256 + threadIdx.x;           // pair index
    const int ppr = KREG / 2;                           // 288
    if (idx >= NV * ppr) return;
    int v  = idx / ppr;
    int kp = idx - v * ppr;
    int k  = kp * 2;                                    // even jn
    int j  = k >> 2;
    int nn = k & 3;                                     // 0 or 2
    float x0 = 0.f, x1 = 0.f;
    if (j < NJ) {
        float w = weights[(size_t)v * NJ + j];
        if (nn == 0) {
            x0 = w * vtemp[v * 3 + 0];
            x1 = w * vtemp[v * 3 + 1];
        } else {
            x0 = w * vtemp[v * 3 + 2];
            x1 = w;
        }
    }
    __nv_bfloat162 h = __float22bfloat162_rn(make_float2(x0, x1));
    float l0 = x0 - __low2float(h);
    float l1 = x1 - __high2float(h);
    __nv_bfloat162 l = __float22bfloat162_rn(make_float2(l0, l1));
    __nv_bfloat16* row = g_A + (size_t)v * (2 * KREG);
    *(__nv_bfloat162*)(row + k)        = h;
    *(__nv_bfloat162*)(row + KREG + k) = l;
}

// ---------------------------------------------------------------------------
// Kernel 3: skinning GEMM via mma.sync bf16. CTA = 128 v x 96 n, 8 warps
// (warp tile 32 x 48). Both A and B cp.async staged, double buffered.
// ---------------------------------------------------------------------------
__global__ void __launch_bounds__(256, 2) skin_mma_kernel(float* __restrict__ out_V) {
    extern __shared__ __align__(16) char smem[];
    uint32_t sbase = (uint32_t)__cvta_generic_to_shared(smem);

    int tid  = threadIdx.x;
    int wid  = tid >> 5;
    int lane = tid & 31;
    int wm   = wid & 3;               // warp m-tile: rows [wm*32, +32)
    int wn   = wid >> 2;              // warp n-tile: cols [wn*48, +48)
    int v0   = blockIdx.x * MT_CTA;
    int n0   = blockIdx.y * NT_CTA;
    int b0   = blockIdx.y * 32;

    const uint32_t a_off[2] = {SO_A0, SO_A1};
    const uint32_t b_off[2] = {SO_B0, SO_B1};

    // chunk c -> A k'-offset: regions 0,1 read Ah, region 2 reads Al
    auto a_koff = [](int c) -> int {
        int r = c / 9, cc = c - 9 * r;
        return (r == 2 ? KREG : 0) + cc * 64;
    };

    // ---- staging via cp.async (SW128 swizzled) ----
    auto stage = [&](int c, int buf) {
        // A: 128 rows x 128 B = 1024 x 16B, 4 per thread
        uint32_t adst = sbase + a_off[buf];
        const char* asrc = (const char*)(g_A + (size_t)v0 * (2 * KREG) + a_koff(c));
        #pragma unroll
        for (int i = 0; i < 4; i++) {
            int idx = tid + i * 256;            // < 1024
            int row = idx >> 3;
            int g   = idx & 7;
            uint32_t off = (uint32_t)(row * 128 + g * 16);
            uint32_t swz = off ^ ((off >> 3) & 0x70);
            cpa16(adst + swz, asrc + (size_t)row * (2 * KREG * 2) + g * 16);
        }
        // B: 96 rows x 128 B = 768 x 16B, 3 per thread
        uint32_t bdst = sbase + b_off[buf];
        const char* bsrc = (const char*)g_B + (size_t)2 * ((size_t)n0 * KTOT + c * 64);
        #pragma unroll
        for (int i = 0; i < 3; i++) {
            int idx = tid + i * 256;            // < 768
            int row = idx >> 3;
            int g   = idx & 7;
            uint32_t off = (uint32_t)(row * 128 + g * 16);
            uint32_t swz = off ^ ((off >> 3) & 0x70);
            cpa16(bdst + swz, bsrc + (size_t)row * (KTOT * 2) + g * 16);
        }
        cpa_commit();
    };

    float acc[2][6][4];
    #pragma unroll
    for (int fm = 0; fm < 2; fm++)
        #pragma unroll
        for (int fn = 0; fn < 6; fn++)
            acc[fm][fn][0] = acc[fm][fn][1] = acc[fm][fn][2] = acc[fm][fn][3] = 0.f;

    // prologue
    stage(0, 0);
    cpa_wait0();
    __syncthreads();

    for (int c = 0; c < NCHUNK; c++) {
        int buf = c & 1;
        if (c + 1 < NCHUNK) stage(c + 1, buf ^ 1);

        uint32_t aBase = sbase + a_off[buf];
        uint32_t bBase = sbase + b_off[buf];

        #pragma unroll
        for (int ks = 0; ks < 4; ks++) {
            uint32_t afr[2][4];
            #pragma unroll
            for (int fm = 0; fm < 2; fm++) {
                int row = wm * 32 + fm * 16 + (lane & 15);
                uint32_t kb = (uint32_t)(ks * 32 + ((lane >> 4) << 4));
                uint32_t addr = aBase + (uint32_t)(row * 128) + (kb ^ (uint32_t)((row & 7) << 4));
                ldsm_x4(addr, afr[fm]);
            }
            uint32_t bfr[6][2];
            #pragma unroll
            for (int fp = 0; fp < 3; fp++) {
                int mi = lane >> 3;
                int nrow = wn * 48 + fp * 16 + ((mi >> 1) << 3) + (lane & 7);
                uint32_t kb = (uint32_t)(ks * 32 + ((mi & 1) << 4));
                uint32_t addr = bBase + (uint32_t)(nrow * 128) + (kb ^ (uint32_t)((nrow & 7) << 4));
                uint32_t rb[4];
                ldsm_x4(addr, rb);
                bfr[2 * fp][0]     = rb[0];
                bfr[2 * fp][1]     = rb[1];
                bfr[2 * fp + 1][0] = rb[2];
                bfr[2 * fp + 1][1] = rb[3];
            }
            #pragma unroll
            for (int fm = 0; fm < 2; fm++)
                #pragma unroll
                for (int fn = 0; fn < 6; fn++)
                    mma16816(acc[fm][fn], afr[fm], bfr[fn]);
        }

        if (c + 1 < NCHUNK) cpa_wait0();
        __syncthreads();
    }

    // ---- epilogue: acc -> SMEM fp32 tile -> global (coalesced) ----
    float* ep = (float*)smem;
    #pragma unroll
    for (int fm = 0; fm < 2; fm++) {
        #pragma unroll
        for (int fn = 0; fn < 6; fn++) {
            int v = wm * 32 + fm * 16 + (lane >> 2);
            int n = wn * 48 + fn * 8 + ((lane & 3) << 1);
            *(float2*)&ep[v * EP_STRIDE + n] = make_float2(acc[fm][fn][0], acc[fm][fn][1]);
            *(float2*)&ep[(v + 8) * EP_STRIDE + n] = make_float2(acc[fm][fn][2], acc[fm][fn][3]);
        }
    }
    __syncthreads();

    int vv = tid & 127;
    int bh = tid >> 7;
    if (v0 + vv < NV) {
        const float* row = ep + vv * EP_STRIDE;
        #pragma unroll
        for (int i = 0; i < 16; i++) {
            int bl = bh * 16 + i;
            int bg = b0 + bl;
            float f0 = row[bl * 3 + 0];
            float f1 = row[bl * 3 + 1];
            float f2 = row[bl * 3 + 2];
            float* o = out_V + ((size_t)bg * NV + (v0 + vv)) * 3;
            o[0] = f0; o[1] = f1; o[2] = f2;
        }
    }
}

// ---------------------------------------------------------------------------
extern "C" void kernel_launch(void* const* d_in, const int* in_sizes, int n_in,
                              void* d_out, int out_size) {
    const float* pose        = (const float*)d_in[0];
    const float* bone_len    = (const float*)d_in[1];
    const float* cbl         = (const float*)d_in[2];
    const float* trans       = (const float*)d_in[3];
    const float* scale       = (const float*)d_in[4];
    const float* v_template  = (const float*)d_in[5];
    const float* t_pose      = (const float*)d_in[6];
    const float* weights     = (const float*)d_in[7];
    const int*   parent      = (const int*)d_in[8];
    const int*   bone_mapper = (const int*)d_in[9];

    float* out   = (float*)d_out;
    float* out_V = out;                                  // [B, NV, 3]
    float* out_J = out + (size_t)BATCH * NV * 3;         // [B, NJ, 3]

    skeleton_kernel<<<BATCH / 4, 128>>>(pose, bone_len, cbl, trans, scale,
                                        t_pose, parent, bone_mapper, out_J);

    {
        int pairs = NTOT * (KTOT / 2);
        pack_B_kernel<<<(pairs + 255) / 256, 256>>>();
    }
    {
        int pairs = NV * (KREG / 2);
        pack_A_kernel<<<(pairs + 255) / 256, 256>>>(v_template, weights);
    }

    static int configured = 0;
    if (!configured) {
        cudaFuncSetAttribute(skin_mma_kernel,
                             cudaFuncAttributeMaxDynamicSharedMemorySize, SMEM_BYTES);
        configured = 1;
    }
    dim3 sg((NV + MT_CTA - 1) / MT_CTA, NTOT / NT_CTA);
    skin_mma_kernel<<<sg, 256, SMEM_BYTES>>>(out_V);
}